// round 16
// baseline (speedup 1.0000x reference)
#include <cuda_runtime.h>
#include <math.h>

#define BDIM 8
#define LDIM 1024
#define DDIM 512
#define NST  16
#define NMEL 40
#define NCH  32
#define TCH  (LDIM/NCH)   // 32
#define ROWW 40           // [0]=dtsum, [4..19]=B_eff, [20..35]=C
#define FIXW 20           // k_fix staging row: [0]=dts, [4..19]=C
#define FIX_CUT 2e-3f     // decay cutoff; R15 measured rel_err 5.7e-7 at 1e-4
                          // (indistinguishable from baseline) -> bound is loose,
                          // 2e-3 predicted to realize ~1e-5..1e-4 aggregate error

typedef unsigned long long u64;

// Scratch (device globals; allocations are forbidden)
__device__ float g_row [BDIM*LDIM*ROWW];            // 1.31 MB
__device__ float g_hend[BDIM*NCH*NST*DDIM];         // 8 MB
__device__ float g_hin [BDIM*NCH*NST*DDIM];         // 8 MB
__device__ float g_cend[BDIM*NCH*DDIM];             // 0.5 MB

__device__ __forceinline__ float fex2(float x){
    float r; asm("ex2.approx.f32 %0,%1;" : "=f"(r) : "f"(x)); return r;
}
__device__ __forceinline__ float softplusf(float z){
    return (z > 15.f) ? z : __logf(1.f + __expf(z));
}
__device__ __forceinline__ u64 pack2(float lo, float hi){
    u64 r; asm("mov.b64 %0,{%1,%2};" : "=l"(r) : "f"(lo), "f"(hi)); return r;
}
__device__ __forceinline__ void unpack2(u64 v, float &lo, float &hi){
    asm("mov.b64 {%0,%1},%2;" : "=f"(lo), "=f"(hi) : "l"(v));
}
__device__ __forceinline__ u64 fma2(u64 a, u64 b, u64 c){
    u64 d; asm("fma.rn.f32x2 %0,%1,%2,%3;" : "=l"(d) : "l"(a), "l"(b), "l"(c)); return d;
}
__device__ __forceinline__ u64 mul2(u64 a, u64 b){
    u64 d; asm("mul.rn.f32x2 %0,%1,%2;" : "=l"(d) : "l"(a), "l"(b)); return d;
}

__device__ __forceinline__ bool load_A2(const float* __restrict__ Alog, int d,
                                        float (&A2)[NST], float &a1)
{
    const float LOG2E = 1.4426950408889634f;
    const float4* A4 = reinterpret_cast<const float4*>(Alog + d*NST);
    float al[NST];
    #pragma unroll
    for (int q = 0; q < 4; ++q) {
        float4 v = A4[q];
        al[4*q+0]=v.x; al[4*q+1]=v.y; al[4*q+2]=v.z; al[4*q+3]=v.w;
    }
    #pragma unroll
    for (int n = 0; n < NST; ++n)
        A2[n] = -__expf(al[n]) * LOG2E;
    a1 = A2[0];
    bool ok = true;
    #pragma unroll
    for (int n = 0; n < NST; ++n) {
        float e = a1 * (float)(n+1);
        ok = ok && (fabsf(A2[n] - e) <= 1e-5f*fabsf(e) + 1e-7f);
    }
    return __all_sync(0xffffffffu, ok);
}

// Build pw[k] = (p^(2k+1), p^(2k+2)) with two depth-4 chains.
__device__ __forceinline__ void build_pw(float p, u64 (&pw)[8])
{
    float p2s = p * p;
    pw[0] = pack2(p, p2s);
    u64 s2 = pack2(p2s, p2s);
    u64 s4 = mul2(s2, s2);
    pw[1] = mul2(pw[0], s2);
    pw[2] = mul2(pw[0], s4);
    pw[3] = mul2(pw[1], s4);
    pw[4] = mul2(pw[2], s4);
    pw[5] = mul2(pw[3], s4);
    pw[6] = mul2(pw[4], s4);
    pw[7] = mul2(pw[5], s4);
}

// ---------------- pass 0: per-(b,l) projections ----------------
#define SMEM_KROW_FLOATS (33*512 + NMEL*17 + 32)
__global__ __launch_bounds__(256) void k_row(
    const float* __restrict__ x,  const float* __restrict__ snr,
    const float* __restrict__ xw, const float* __restrict__ sw,
    const float* __restrict__ sb, const float* __restrict__ alpha_p,
    const float* __restrict__ gf_p)
{
    extern __shared__ float smem[];
    float* s_w   = smem;                    // [33][512]
    float* s_swT = smem + 33*512;           // [NMEL][17]
    float* s_sb  = s_swT + NMEL*17;         // [17]

    {
        const float4* w4 = reinterpret_cast<const float4*>(xw);
        float4* s4 = reinterpret_cast<float4*>(s_w);
        for (int i = threadIdx.x; i < 33*128; i += 256) s4[i] = w4[i];
    }
    for (int i = threadIdx.x; i < 17*NMEL; i += 256) {
        int p = i / NMEL, m = i % NMEL;
        s_swT[m*17 + p] = sw[i];
    }
    if (threadIdx.x < 17) s_sb[threadIdx.x] = sb[threadIdx.x];
    __syncthreads();

    const int lane = threadIdx.x & 31;
    const int gi   = lane >> 3;
    const int li   = lane & 7;
    const int warp = (blockIdx.x * blockDim.x + threadIdx.x) >> 5;
    const int r    = warp*4 + gi;
    const float alpha = *alpha_p;
    const float gf    = *gf_p;

    const ulonglong2* X2 = reinterpret_cast<const ulonglong2*>(x);

    u64 acc2[33];
    #pragma unroll
    for (int p = 0; p < 33; ++p) acc2[p] = 0ull;

    for (int j = 0; j < 16; ++j) {
        int k4 = li + 8*j;
        ulonglong2 xv = X2[(size_t)r*128 + k4];
        #pragma unroll
        for (int p = 0; p < 33; ++p) {
            ulonglong2 wv = *reinterpret_cast<const ulonglong2*>(s_w + p*512 + k4*4);
            acc2[p] = fma2(xv.x, wv.x, acc2[p]);
            acc2[p] = fma2(xv.y, wv.y, acc2[p]);
        }
    }

    float acc[33];
    #pragma unroll
    for (int p = 0; p < 33; ++p) {
        float lo, hi; unpack2(acc2[p], lo, hi);
        float v = lo + hi;
        v += __shfl_xor_sync(0xffffffffu, v, 4);
        v += __shfl_xor_sync(0xffffffffu, v, 2);
        v += __shfl_xor_sync(0xffffffffu, v, 1);
        acc[p] = v;
    }

    float s[3];
    int   pl[3] = {li, li+8, li+16};
    #pragma unroll
    for (int q = 0; q < 3; ++q) s[q] = (pl[q] <= 16) ? s_sb[pl[q]] : 0.f;
    const float* sr = snr + (size_t)r*NMEL;
    #pragma unroll
    for (int m = 0; m < NMEL; ++m) {
        float sv = sr[m];
        #pragma unroll
        for (int q = 0; q < 3; ++q)
            if (pl[q] <= 16) s[q] = fmaf(sv, s_swT[m*17 + pl[q]], s[q]);
    }

    float* row = g_row + (size_t)r*ROWW;
    #pragma unroll
    for (int q = 0; q < 5; ++q) {
        int p = li + 8*q;
        if (p > 32) break;
        if (p == 0) {
            row[0] = acc[0] + s[0];
        } else if (p <= 16) {
            float sig = 1.f / (1.f + __expf(-s[q]));
            float fac = 1.f - alpha + alpha * (gf + (1.f - gf) * sig);
            row[p+3] = acc[p] * fac;
        } else {
            row[p+3] = acc[p];
        }
    }
}

// ---------------- pass 1: chunk-local scan with local output ----------------
__global__ __launch_bounds__(128, 8) void k_scan1(
    const float* __restrict__ x,   const float* __restrict__ Alog,
    const float* __restrict__ dtw, const float* __restrict__ dtb,
    const float* __restrict__ Dprm, float* __restrict__ out)
{
    __shared__ float s_row[TCH*ROWW];
    const int bid = blockIdx.x;
    const int b  = bid >> 7;
    const int c  = (bid >> 2) & (NCH-1);
    const int dh = bid & 3;
    const int d  = dh*128 + threadIdx.x;

    size_t rbase = (size_t)b*LDIM + (size_t)c*TCH;
    {
        const float4* g4 = reinterpret_cast<const float4*>(g_row + rbase*ROWW);
        float4* s4p = reinterpret_cast<float4*>(s_row);
        for (int i = threadIdx.x; i < TCH*ROWW/4; i += 128) s4p[i] = g4[i];
    }
    __syncthreads();

    float A2[NST]; float a1;
    bool trick = load_A2(Alog, d, A2, a1);
    const float wd = dtw[d], bd = dtb[d], Dp = Dprm[d];

    const float* xrow = x   + rbase*DDIM + d;
    float*       orow = out + rbase*DDIM + d;

    float cum = 0.f;
    u64 h2[8];
    #pragma unroll
    for (int k = 0; k < 8; ++k) h2[k] = 0ull;

    if (trick) {
        for (int g = 0; g < TCH/4; ++g) {
            float xq[4];
            #pragma unroll
            for (int u = 0; u < 4; ++u)
                xq[u] = xrow[(size_t)(g*4 + u)*DDIM];
            #pragma unroll
            for (int u = 0; u < 4; ++u) {
                const int t = g*4 + u;
                const float* srow = s_row + t*ROWW;
                float del = softplusf(fmaf(srow[0], wd, bd));
                cum += del;
                float dx  = del * xq[u];
                u64 dx2 = pack2(dx, dx);
                u64 pw[8]; build_pw(fex2(a1*del), pw);

                ulonglong2 Bq0 = *reinterpret_cast<const ulonglong2*>(srow+4);
                ulonglong2 Bq1 = *reinterpret_cast<const ulonglong2*>(srow+8);
                ulonglong2 Bq2 = *reinterpret_cast<const ulonglong2*>(srow+12);
                ulonglong2 Bq3 = *reinterpret_cast<const ulonglong2*>(srow+16);
                ulonglong2 Cq0 = *reinterpret_cast<const ulonglong2*>(srow+20);
                ulonglong2 Cq1 = *reinterpret_cast<const ulonglong2*>(srow+24);
                ulonglong2 Cq2 = *reinterpret_cast<const ulonglong2*>(srow+28);
                ulonglong2 Cq3 = *reinterpret_cast<const ulonglong2*>(srow+32);
                u64 B2[8] = {Bq0.x, Bq0.y, Bq1.x, Bq1.y, Bq2.x, Bq2.y, Bq3.x, Bq3.y};
                u64 C2[8] = {Cq0.x, Cq0.y, Cq1.x, Cq1.y, Cq2.x, Cq2.y, Cq3.x, Cq3.y};

                u64 y2 = pack2(Dp * xq[u], 0.f);
                #pragma unroll
                for (int k = 0; k < 8; ++k) {
                    h2[k] = fma2(pw[k], h2[k], mul2(dx2, B2[k]));
                    y2    = fma2(h2[k], C2[k], y2);
                }
                float ylo, yhi; unpack2(y2, ylo, yhi);
                orow[(size_t)t*DDIM] = ylo + yhi;
            }
        }
    } else {
        float h[NST];
        #pragma unroll
        for (int n = 0; n < NST; ++n) h[n] = 0.f;
        for (int t = 0; t < TCH; ++t) {
            const float* srow = s_row + t*ROWW;
            float del = softplusf(fmaf(srow[0], wd, bd));
            cum += del;
            float xv  = xrow[(size_t)t*DDIM];
            float dx  = del * xv;
            float y   = Dp * xv;
            #pragma unroll
            for (int n = 0; n < NST; ++n) {
                h[n] = fmaf(fex2(A2[n]*del), h[n], dx * srow[4+n]);
                y    = fmaf(h[n], srow[20+n], y);
            }
            orow[(size_t)t*DDIM] = y;
        }
        #pragma unroll
        for (int k = 0; k < 8; ++k) h2[k] = pack2(h[2*k], h[2*k+1]);
    }

    size_t hb = ((size_t)(b*NCH + c)*NST)*DDIM + d;
    #pragma unroll
    for (int k = 0; k < 8; ++k) {
        float lo, hi; unpack2(h2[k], lo, hi);
        g_hend[hb + (size_t)(2*k)*DDIM]   = lo;
        g_hend[hb + (size_t)(2*k+1)*DDIM] = hi;
    }
    g_cend[((size_t)b*NCH + c)*DDIM + d] = cum;
}

// ---------------- pass 2: cross-chunk combine ----------------
__global__ __launch_bounds__(256) void k_comb(const float* __restrict__ Alog)
{
    int tid = blockIdx.x * blockDim.x + threadIdx.x;
    int d = tid & (DDIM-1);
    int n = (tid >> 9) & (NST-1);
    int b = tid >> 13;

    const float LOG2E = 1.4426950408889634f;
    float a = -__expf(Alog[d*NST + n]) * LOG2E;

    float h = 0.f;
    for (int c = 0; c < NCH; c += 4) {
        float ce[4], he[4];
        size_t hbs[4];
        #pragma unroll
        for (int j = 0; j < 4; ++j) {
            hbs[j] = ((size_t)(b*NCH + c + j)*NST + n)*DDIM + d;
            ce[j] = g_cend[((size_t)b*NCH + c + j)*DDIM + d];
            he[j] = g_hend[hbs[j]];
        }
        #pragma unroll
        for (int j = 0; j < 4; ++j) {
            g_hin[hbs[j]] = h;
            h = fmaf(fex2(a * ce[j]), h, he[j]);
        }
    }
}

// ---------------- pass 3: decaying cross-chunk correction ----------------
__global__ __launch_bounds__(128, 8) void k_fix(
    const float* __restrict__ Alog, const float* __restrict__ dtw,
    const float* __restrict__ dtb,  float* __restrict__ out)
{
    const int bid = blockIdx.x;
    const int b  = bid >> 7;
    const int c  = (bid >> 2) & (NCH-1);
    const int dh = bid & 3;
    if (c == 0) return;                    // hin = 0
    const int d  = dh*128 + threadIdx.x;

    __shared__ float s_fix[TCH*FIXW];      // [t]: [0]=dts, [4..19]=C
    size_t rbase = (size_t)b*LDIM + (size_t)c*TCH;
    {
        const float* gr = g_row + rbase*ROWW;
        for (int i = threadIdx.x; i < TCH*4; i += 128) {
            int t = i >> 2, q = i & 3;
            *reinterpret_cast<float4*>(s_fix + t*FIXW + 4 + 4*q) =
                *reinterpret_cast<const float4*>(gr + (size_t)t*ROWW + 20 + 4*q);
        }
        if (threadIdx.x < TCH)
            s_fix[threadIdx.x*FIXW] = gr[(size_t)threadIdx.x*ROWW];
    }
    __syncthreads();

    float A2[NST]; float a1;
    bool trick = load_A2(Alog, d, A2, a1);
    const float wd = dtw[d], bd = dtb[d];
    float amax = A2[0];
    #pragma unroll
    for (int n = 1; n < NST; ++n) amax = fmaxf(amax, A2[n]);

    float hin[NST];
    u64 hi2[8];
    float hsum = 0.f;
    {
        size_t hb = ((size_t)(b*NCH + c)*NST)*DDIM + d;
        #pragma unroll
        for (int n = 0; n < NST; ++n) {
            hin[n] = g_hin[hb + (size_t)n*DDIM];
            hsum  += fabsf(hin[n]);
        }
        #pragma unroll
        for (int k = 0; k < 8; ++k) hi2[k] = pack2(hin[2*k], hin[2*k+1]);
    }

    float* orow = out + rbase*DDIM + d;
    float cum = 0.f;

    if (trick) {
        for (int g = 0; g < TCH/4; ++g) {
            float oq[4];
            #pragma unroll
            for (int u = 0; u < 4; ++u)
                oq[u] = orow[(size_t)(g*4 + u)*DDIM];
            #pragma unroll
            for (int u = 0; u < 4; ++u) {
                const int t = g*4 + u;
                const float* srow = s_fix + t*FIXW;
                cum += softplusf(fmaf(srow[0], wd, bd));
                float q = fex2(a1 * cum);
                bool live = (q * hsum > FIX_CUT);
                if (!__any_sync(0xffffffffu, live)) return;
                u64 pw[8]; build_pw(q, pw);
                ulonglong2 Cq0 = *reinterpret_cast<const ulonglong2*>(srow+4);
                ulonglong2 Cq1 = *reinterpret_cast<const ulonglong2*>(srow+8);
                ulonglong2 Cq2 = *reinterpret_cast<const ulonglong2*>(srow+12);
                ulonglong2 Cq3 = *reinterpret_cast<const ulonglong2*>(srow+16);
                u64 C2[8] = {Cq0.x, Cq0.y, Cq1.x, Cq1.y, Cq2.x, Cq2.y, Cq3.x, Cq3.y};
                u64 acc = 0ull;
                #pragma unroll
                for (int k = 0; k < 8; ++k)
                    acc = fma2(mul2(hi2[k], pw[k]), C2[k], acc);
                float lo, hi; unpack2(acc, lo, hi);
                orow[(size_t)t*DDIM] = oq[u] + lo + hi;
            }
        }
    } else {
        for (int t = 0; t < TCH; ++t) {
            const float* srow = s_fix + t*FIXW;
            cum += softplusf(fmaf(srow[0], wd, bd));
            float qm  = fex2(amax * cum);
            bool live = (qm * hsum > FIX_CUT);
            if (!__any_sync(0xffffffffu, live)) return;
            float corr = 0.f;
            #pragma unroll
            for (int n = 0; n < NST; ++n)
                corr = fmaf(fex2(A2[n]*cum) * hin[n], srow[4+n], corr);
            orow[(size_t)t*DDIM] += corr;
        }
    }
}

extern "C" void kernel_launch(void* const* d_in, const int* in_sizes, int n_in,
                              void* d_out, int out_size)
{
    const float* x    = (const float*)d_in[0];
    const float* snr  = (const float*)d_in[1];
    const float* xw   = (const float*)d_in[2];
    const float* sw   = (const float*)d_in[3];
    const float* sb   = (const float*)d_in[4];
    const float* dtw  = (const float*)d_in[5];
    const float* dtb  = (const float*)d_in[6];
    const float* Alog = (const float*)d_in[7];
    const float* Dp   = (const float*)d_in[8];
    const float* al   = (const float*)d_in[9];
    const float* gf   = (const float*)d_in[10];
    float* out = (float*)d_out;

    static bool attr_set = false;
    if (!attr_set) {
        cudaFuncSetAttribute(k_row, cudaFuncAttributeMaxDynamicSharedMemorySize,
                             SMEM_KROW_FLOATS * (int)sizeof(float));
        attr_set = true;
    }

    k_row  <<<256, 256, SMEM_KROW_FLOATS*sizeof(float)>>>(x, snr, xw, sw, sb, al, gf);
    k_scan1<<<1024, 128>>>(x, Alog, dtw, dtb, Dp, out);
    k_comb <<<256, 256>>>(Alog);
    k_fix  <<<1024, 128>>>(Alog, dtw, dtb, out);
}

// round 17
// speedup vs baseline: 1.0401x; 1.0401x over previous
#include <cuda_runtime.h>
#include <math.h>

#define BDIM 8
#define LDIM 1024
#define DDIM 512
#define NST  16
#define NMEL 40
#define NCH  32
#define TCH  (LDIM/NCH)   // 32
#define ROWW 40           // [0]=dtsum, [4..19]=B_eff, [20..35]=C
#define FIXW 20           // k_fix staging row: [0]=dts, [4..19]=C
#define FIX_CUT 2e-3f

typedef unsigned long long u64;

// Scratch (device globals; allocations are forbidden)
__device__ float g_row [BDIM*LDIM*ROWW];            // 1.31 MB
__device__ float g_hend[BDIM*NCH*NST*DDIM];         // 8 MB
__device__ float g_cend[BDIM*NCH*DDIM];             // 0.5 MB

__device__ __forceinline__ float fex2(float x){
    float r; asm("ex2.approx.f32 %0,%1;" : "=f"(r) : "f"(x)); return r;
}
__device__ __forceinline__ float softplusf(float z){
    return (z > 15.f) ? z : __logf(1.f + __expf(z));
}
__device__ __forceinline__ u64 pack2(float lo, float hi){
    u64 r; asm("mov.b64 %0,{%1,%2};" : "=l"(r) : "f"(lo), "f"(hi)); return r;
}
__device__ __forceinline__ void unpack2(u64 v, float &lo, float &hi){
    asm("mov.b64 {%0,%1},%2;" : "=f"(lo), "=f"(hi) : "l"(v));
}
__device__ __forceinline__ u64 fma2(u64 a, u64 b, u64 c){
    u64 d; asm("fma.rn.f32x2 %0,%1,%2,%3;" : "=l"(d) : "l"(a), "l"(b), "l"(c)); return d;
}
__device__ __forceinline__ u64 mul2(u64 a, u64 b){
    u64 d; asm("mul.rn.f32x2 %0,%1,%2;" : "=l"(d) : "l"(a), "l"(b)); return d;
}

__device__ __forceinline__ bool load_A2(const float* __restrict__ Alog, int d,
                                        float (&A2)[NST], float &a1)
{
    const float LOG2E = 1.4426950408889634f;
    const float4* A4 = reinterpret_cast<const float4*>(Alog + d*NST);
    float al[NST];
    #pragma unroll
    for (int q = 0; q < 4; ++q) {
        float4 v = A4[q];
        al[4*q+0]=v.x; al[4*q+1]=v.y; al[4*q+2]=v.z; al[4*q+3]=v.w;
    }
    #pragma unroll
    for (int n = 0; n < NST; ++n)
        A2[n] = -__expf(al[n]) * LOG2E;
    a1 = A2[0];
    bool ok = true;
    #pragma unroll
    for (int n = 0; n < NST; ++n) {
        float e = a1 * (float)(n+1);
        ok = ok && (fabsf(A2[n] - e) <= 1e-5f*fabsf(e) + 1e-7f);
    }
    return __all_sync(0xffffffffu, ok);
}

// Build pw[k] = (p^(2k+1), p^(2k+2)) with two depth-4 chains.
__device__ __forceinline__ void build_pw(float p, u64 (&pw)[8])
{
    float p2s = p * p;
    pw[0] = pack2(p, p2s);
    u64 s2 = pack2(p2s, p2s);
    u64 s4 = mul2(s2, s2);
    pw[1] = mul2(pw[0], s2);
    pw[2] = mul2(pw[0], s4);
    pw[3] = mul2(pw[1], s4);
    pw[4] = mul2(pw[2], s4);
    pw[5] = mul2(pw[3], s4);
    pw[6] = mul2(pw[4], s4);
    pw[7] = mul2(pw[5], s4);
}

// ---------------- pass 0: per-(b,l) projections ----------------
#define SMEM_KROW_FLOATS (33*512 + NMEL*17 + 32)
__global__ __launch_bounds__(256) void k_row(
    const float* __restrict__ x,  const float* __restrict__ snr,
    const float* __restrict__ xw, const float* __restrict__ sw,
    const float* __restrict__ sb, const float* __restrict__ alpha_p,
    const float* __restrict__ gf_p)
{
    extern __shared__ float smem[];
    float* s_w   = smem;                    // [33][512]
    float* s_swT = smem + 33*512;           // [NMEL][17]
    float* s_sb  = s_swT + NMEL*17;         // [17]

    {
        const float4* w4 = reinterpret_cast<const float4*>(xw);
        float4* s4 = reinterpret_cast<float4*>(s_w);
        for (int i = threadIdx.x; i < 33*128; i += 256) s4[i] = w4[i];
    }
    for (int i = threadIdx.x; i < 17*NMEL; i += 256) {
        int p = i / NMEL, m = i % NMEL;
        s_swT[m*17 + p] = sw[i];
    }
    if (threadIdx.x < 17) s_sb[threadIdx.x] = sb[threadIdx.x];
    __syncthreads();

    const int lane = threadIdx.x & 31;
    const int gi   = lane >> 3;
    const int li   = lane & 7;
    const int warp = (blockIdx.x * blockDim.x + threadIdx.x) >> 5;
    const int r    = warp*4 + gi;
    const float alpha = *alpha_p;
    const float gf    = *gf_p;

    const ulonglong2* X2 = reinterpret_cast<const ulonglong2*>(x);

    u64 acc2[33];
    #pragma unroll
    for (int p = 0; p < 33; ++p) acc2[p] = 0ull;

    for (int j = 0; j < 16; ++j) {
        int k4 = li + 8*j;
        ulonglong2 xv = X2[(size_t)r*128 + k4];
        #pragma unroll
        for (int p = 0; p < 33; ++p) {
            ulonglong2 wv = *reinterpret_cast<const ulonglong2*>(s_w + p*512 + k4*4);
            acc2[p] = fma2(xv.x, wv.x, acc2[p]);
            acc2[p] = fma2(xv.y, wv.y, acc2[p]);
        }
    }

    float acc[33];
    #pragma unroll
    for (int p = 0; p < 33; ++p) {
        float lo, hi; unpack2(acc2[p], lo, hi);
        float v = lo + hi;
        v += __shfl_xor_sync(0xffffffffu, v, 4);
        v += __shfl_xor_sync(0xffffffffu, v, 2);
        v += __shfl_xor_sync(0xffffffffu, v, 1);
        acc[p] = v;
    }

    float s[3];
    int   pl[3] = {li, li+8, li+16};
    #pragma unroll
    for (int q = 0; q < 3; ++q) s[q] = (pl[q] <= 16) ? s_sb[pl[q]] : 0.f;
    const float* sr = snr + (size_t)r*NMEL;
    #pragma unroll
    for (int m = 0; m < NMEL; ++m) {
        float sv = sr[m];
        #pragma unroll
        for (int q = 0; q < 3; ++q)
            if (pl[q] <= 16) s[q] = fmaf(sv, s_swT[m*17 + pl[q]], s[q]);
    }

    float* row = g_row + (size_t)r*ROWW;
    #pragma unroll
    for (int q = 0; q < 5; ++q) {
        int p = li + 8*q;
        if (p > 32) break;
        if (p == 0) {
            row[0] = acc[0] + s[0];
        } else if (p <= 16) {
            float sig = 1.f / (1.f + __expf(-s[q]));
            float fac = 1.f - alpha + alpha * (gf + (1.f - gf) * sig);
            row[p+3] = acc[p] * fac;
        } else {
            row[p+3] = acc[p];
        }
    }
}

// ---------------- pass 1: chunk-local scan with local output ----------------
__global__ __launch_bounds__(128, 8) void k_scan1(
    const float* __restrict__ x,   const float* __restrict__ Alog,
    const float* __restrict__ dtw, const float* __restrict__ dtb,
    const float* __restrict__ Dprm, float* __restrict__ out)
{
    __shared__ float s_row[TCH*ROWW];
    const int bid = blockIdx.x;
    const int b  = bid >> 7;
    const int c  = (bid >> 2) & (NCH-1);
    const int dh = bid & 3;
    const int d  = dh*128 + threadIdx.x;

    size_t rbase = (size_t)b*LDIM + (size_t)c*TCH;
    {
        const float4* g4 = reinterpret_cast<const float4*>(g_row + rbase*ROWW);
        float4* s4p = reinterpret_cast<float4*>(s_row);
        for (int i = threadIdx.x; i < TCH*ROWW/4; i += 128) s4p[i] = g4[i];
    }
    __syncthreads();

    float A2[NST]; float a1;
    bool trick = load_A2(Alog, d, A2, a1);
    const float wd = dtw[d], bd = dtb[d], Dp = Dprm[d];

    const float* xrow = x   + rbase*DDIM + d;
    float*       orow = out + rbase*DDIM + d;

    float cum = 0.f;
    u64 h2[8];
    #pragma unroll
    for (int k = 0; k < 8; ++k) h2[k] = 0ull;

    if (trick) {
        for (int g = 0; g < TCH/4; ++g) {
            float xq[4];
            #pragma unroll
            for (int u = 0; u < 4; ++u)
                xq[u] = xrow[(size_t)(g*4 + u)*DDIM];
            #pragma unroll
            for (int u = 0; u < 4; ++u) {
                const int t = g*4 + u;
                const float* srow = s_row + t*ROWW;
                float del = softplusf(fmaf(srow[0], wd, bd));
                cum += del;
                float dx  = del * xq[u];
                u64 dx2 = pack2(dx, dx);
                u64 pw[8]; build_pw(fex2(a1*del), pw);

                ulonglong2 Bq0 = *reinterpret_cast<const ulonglong2*>(srow+4);
                ulonglong2 Bq1 = *reinterpret_cast<const ulonglong2*>(srow+8);
                ulonglong2 Bq2 = *reinterpret_cast<const ulonglong2*>(srow+12);
                ulonglong2 Bq3 = *reinterpret_cast<const ulonglong2*>(srow+16);
                ulonglong2 Cq0 = *reinterpret_cast<const ulonglong2*>(srow+20);
                ulonglong2 Cq1 = *reinterpret_cast<const ulonglong2*>(srow+24);
                ulonglong2 Cq2 = *reinterpret_cast<const ulonglong2*>(srow+28);
                ulonglong2 Cq3 = *reinterpret_cast<const ulonglong2*>(srow+32);
                u64 B2[8] = {Bq0.x, Bq0.y, Bq1.x, Bq1.y, Bq2.x, Bq2.y, Bq3.x, Bq3.y};
                u64 C2[8] = {Cq0.x, Cq0.y, Cq1.x, Cq1.y, Cq2.x, Cq2.y, Cq3.x, Cq3.y};

                u64 y2 = pack2(Dp * xq[u], 0.f);
                #pragma unroll
                for (int k = 0; k < 8; ++k) {
                    h2[k] = fma2(pw[k], h2[k], mul2(dx2, B2[k]));
                    y2    = fma2(h2[k], C2[k], y2);
                }
                float ylo, yhi; unpack2(y2, ylo, yhi);
                orow[(size_t)t*DDIM] = ylo + yhi;
            }
        }
    } else {
        float h[NST];
        #pragma unroll
        for (int n = 0; n < NST; ++n) h[n] = 0.f;
        for (int t = 0; t < TCH; ++t) {
            const float* srow = s_row + t*ROWW;
            float del = softplusf(fmaf(srow[0], wd, bd));
            cum += del;
            float xv  = xrow[(size_t)t*DDIM];
            float dx  = del * xv;
            float y   = Dp * xv;
            #pragma unroll
            for (int n = 0; n < NST; ++n) {
                h[n] = fmaf(fex2(A2[n]*del), h[n], dx * srow[4+n]);
                y    = fmaf(h[n], srow[20+n], y);
            }
            orow[(size_t)t*DDIM] = y;
        }
        #pragma unroll
        for (int k = 0; k < 8; ++k) h2[k] = pack2(h[2*k], h[2*k+1]);
    }

    size_t hb = ((size_t)(b*NCH + c)*NST)*DDIM + d;
    #pragma unroll
    for (int k = 0; k < 8; ++k) {
        float lo, hi; unpack2(h2[k], lo, hi);
        g_hend[hb + (size_t)(2*k)*DDIM]   = lo;
        g_hend[hb + (size_t)(2*k+1)*DDIM] = hi;
    }
    g_cend[((size_t)b*NCH + c)*DDIM + d] = cum;
}

// ---------------- pass 2: decaying cross-chunk correction ----------------
// hin(c) computed in-kernel by two-hop truncation:
//   hin = hend(c-1) + exp(A * cend(c-1)) * hend(c-2)
// The dropped tail is O(exp(A * two full chunks)) ~ 1e-9, far below FIX_CUT.
__global__ __launch_bounds__(128, 8) void k_fix(
    const float* __restrict__ Alog, const float* __restrict__ dtw,
    const float* __restrict__ dtb,  float* __restrict__ out)
{
    const int bid = blockIdx.x;
    const int b  = bid >> 7;
    const int c  = (bid >> 2) & (NCH-1);
    const int dh = bid & 3;
    if (c == 0) return;                    // hin = 0
    const int d  = dh*128 + threadIdx.x;

    __shared__ float s_fix[TCH*FIXW];      // [t]: [0]=dts, [4..19]=C
    size_t rbase = (size_t)b*LDIM + (size_t)c*TCH;
    {
        const float* gr = g_row + rbase*ROWW;
        for (int i = threadIdx.x; i < TCH*4; i += 128) {
            int t = i >> 2, q = i & 3;
            *reinterpret_cast<float4*>(s_fix + t*FIXW + 4 + 4*q) =
                *reinterpret_cast<const float4*>(gr + (size_t)t*ROWW + 20 + 4*q);
        }
        if (threadIdx.x < TCH)
            s_fix[threadIdx.x*FIXW] = gr[(size_t)threadIdx.x*ROWW];
    }
    __syncthreads();

    float A2[NST]; float a1;
    bool trick = load_A2(Alog, d, A2, a1);
    const float wd = dtw[d], bd = dtb[d];
    float amax = A2[0];
    #pragma unroll
    for (int n = 1; n < NST; ++n) amax = fmaxf(amax, A2[n]);

    // two-hop incoming state
    float hin[NST];
    u64 hi2[8];
    float hsum = 0.f;
    {
        size_t hb1 = ((size_t)(b*NCH + c-1)*NST)*DDIM + d;
        float ce1  = g_cend[((size_t)b*NCH + c-1)*DDIM + d];
        float he1[NST], he2[NST];
        #pragma unroll
        for (int n = 0; n < NST; ++n) he1[n] = g_hend[hb1 + (size_t)n*DDIM];
        if (c >= 2) {
            size_t hb2 = ((size_t)(b*NCH + c-2)*NST)*DDIM + d;
            #pragma unroll
            for (int n = 0; n < NST; ++n) he2[n] = g_hend[hb2 + (size_t)n*DDIM];
        } else {
            #pragma unroll
            for (int n = 0; n < NST; ++n) he2[n] = 0.f;
        }
        if (trick) {
            u64 pwq[8]; build_pw(fex2(a1*ce1), pwq);
            #pragma unroll
            for (int k = 0; k < 8; ++k) {
                u64 v = fma2(pwq[k], pack2(he2[2*k], he2[2*k+1]),
                             pack2(he1[2*k], he1[2*k+1]));
                hi2[k] = v;
                float lo, hi; unpack2(v, lo, hi);
                hin[2*k] = lo; hin[2*k+1] = hi;
                hsum += fabsf(lo) + fabsf(hi);
            }
        } else {
            #pragma unroll
            for (int n = 0; n < NST; ++n) {
                hin[n] = fmaf(fex2(A2[n]*ce1), he2[n], he1[n]);
                hsum  += fabsf(hin[n]);
            }
            #pragma unroll
            for (int k = 0; k < 8; ++k) hi2[k] = pack2(hin[2*k], hin[2*k+1]);
        }
    }

    float* orow = out + rbase*DDIM + d;
    float cum = 0.f;

    if (trick) {
        for (int g = 0; g < TCH/4; ++g) {
            float oq[4];
            #pragma unroll
            for (int u = 0; u < 4; ++u)
                oq[u] = orow[(size_t)(g*4 + u)*DDIM];
            #pragma unroll
            for (int u = 0; u < 4; ++u) {
                const int t = g*4 + u;
                const float* srow = s_fix + t*FIXW;
                cum += softplusf(fmaf(srow[0], wd, bd));
                float q = fex2(a1 * cum);
                bool live = (q * hsum > FIX_CUT);
                if (!__any_sync(0xffffffffu, live)) return;
                u64 pw[8]; build_pw(q, pw);
                ulonglong2 Cq0 = *reinterpret_cast<const ulonglong2*>(srow+4);
                ulonglong2 Cq1 = *reinterpret_cast<const ulonglong2*>(srow+8);
                ulonglong2 Cq2 = *reinterpret_cast<const ulonglong2*>(srow+12);
                ulonglong2 Cq3 = *reinterpret_cast<const ulonglong2*>(srow+16);
                u64 C2[8] = {Cq0.x, Cq0.y, Cq1.x, Cq1.y, Cq2.x, Cq2.y, Cq3.x, Cq3.y};
                u64 acc = 0ull;
                #pragma unroll
                for (int k = 0; k < 8; ++k)
                    acc = fma2(mul2(hi2[k], pw[k]), C2[k], acc);
                float lo, hi; unpack2(acc, lo, hi);
                orow[(size_t)t*DDIM] = oq[u] + lo + hi;
            }
        }
    } else {
        for (int t = 0; t < TCH; ++t) {
            const float* srow = s_fix + t*FIXW;
            cum += softplusf(fmaf(srow[0], wd, bd));
            float qm  = fex2(amax * cum);
            bool live = (qm * hsum > FIX_CUT);
            if (!__any_sync(0xffffffffu, live)) return;
            float corr = 0.f;
            #pragma unroll
            for (int n = 0; n < NST; ++n)
                corr = fmaf(fex2(A2[n]*cum) * hin[n], srow[4+n], corr);
            orow[(size_t)t*DDIM] += corr;
        }
    }
}

extern "C" void kernel_launch(void* const* d_in, const int* in_sizes, int n_in,
                              void* d_out, int out_size)
{
    const float* x    = (const float*)d_in[0];
    const float* snr  = (const float*)d_in[1];
    const float* xw   = (const float*)d_in[2];
    const float* sw   = (const float*)d_in[3];
    const float* sb   = (const float*)d_in[4];
    const float* dtw  = (const float*)d_in[5];
    const float* dtb  = (const float*)d_in[6];
    const float* Alog = (const float*)d_in[7];
    const float* Dp   = (const float*)d_in[8];
    const float* al   = (const float*)d_in[9];
    const float* gf   = (const float*)d_in[10];
    float* out = (float*)d_out;

    static bool attr_set = false;
    if (!attr_set) {
        cudaFuncSetAttribute(k_row, cudaFuncAttributeMaxDynamicSharedMemorySize,
                             SMEM_KROW_FLOATS * (int)sizeof(float));
        attr_set = true;
    }

    k_row  <<<256, 256, SMEM_KROW_FLOATS*sizeof(float)>>>(x, snr, xw, sw, sb, al, gf);
    k_scan1<<<1024, 128>>>(x, Alog, dtw, dtb, Dp, out);
    k_fix  <<<1024, 128>>>(Alog, dtw, dtb, out);
}